// round 8
// baseline (speedup 1.0000x reference)
#include <cuda_runtime.h>
#include <cuda_bf16.h>
#include <cuda_fp16.h>
#include <cstdint>

#define N_NODES 50000
#define D 128
#define N_EDGES 625000

// Device-global scratch (allocation-free rule; BSS zero-initialized)
__device__ float g_sum[N_NODES * D];            // re-zeroed by meanconv each run
__device__ float g_deg[N_NODES];                // re-zeroed by meanconv each run
__device__ __half g_xh[N_NODES * D];            // x as fp16 (scatter gather)
__device__ __nv_bfloat16 g_xhi[N_NODES * D];    // x bf16 hi
__device__ __nv_bfloat16 g_xlo[N_NODES * D];    // x bf16 lo
__device__ __nv_bfloat16 g_mhi[N_NODES * D];    // mean bf16 hi
__device__ __nv_bfloat16 g_mlo[N_NODES * D];    // mean bf16 lo
__device__ __nv_bfloat16 g_W[4 * 128 * 128];    // Wl_hi, Wl_lo, Wr_hi, Wr_lo  [mat][k][n]

// ---------------------------------------------------------------------------
// helpers
// ---------------------------------------------------------------------------
__device__ __forceinline__ uint32_t smem_u32(const void* p) {
    uint32_t a;
    asm("{ .reg .u64 t; cvta.to.shared.u64 t, %1; cvt.u32.u64 %0, t; }" : "=r"(a) : "l"(p));
    return a;
}

#define CP_ASYNC16(dst, src) \
    asm volatile("cp.async.cg.shared.global [%0], [%1], 16;" :: "r"(dst), "l"(src))
#define CP_ASYNC16Z(dst, src, sz) \
    asm volatile("cp.async.cg.shared.global [%0], [%1], 16, %2;" :: "r"(dst), "l"(src), "r"(sz))
#define CP_COMMIT() asm volatile("cp.async.commit_group;")
#define CP_WAIT0()  asm volatile("cp.async.wait_group 0;" ::: "memory")

#define LDSM_X4(r, addr) \
    asm volatile("ldmatrix.sync.aligned.m8n8.x4.shared.b16 {%0,%1,%2,%3}, [%4];" \
                 : "=r"((r)[0]), "=r"((r)[1]), "=r"((r)[2]), "=r"((r)[3]) : "r"(addr))
#define LDSM_X4T(r, addr) \
    asm volatile("ldmatrix.sync.aligned.m8n8.x4.trans.shared.b16 {%0,%1,%2,%3}, [%4];" \
                 : "=r"((r)[0]), "=r"((r)[1]), "=r"((r)[2]), "=r"((r)[3]) : "r"(addr))

__device__ __forceinline__ void mma16816(float* d, const uint32_t* a, const uint32_t* b) {
    asm volatile(
        "mma.sync.aligned.m16n8k16.row.col.f32.bf16.bf16.f32 "
        "{%0,%1,%2,%3}, {%4,%5,%6,%7}, {%8,%9}, {%0,%1,%2,%3};"
        : "+f"(d[0]), "+f"(d[1]), "+f"(d[2]), "+f"(d[3])
        : "r"(a[0]), "r"(a[1]), "r"(a[2]), "r"(a[3]), "r"(b[0]), "r"(b[1]));
}

__device__ __forceinline__ uint32_t pack_bf16x2(float a, float b) {
    __nv_bfloat16 ha = __float2bfloat16(a), hb = __float2bfloat16(b);
    return (uint32_t)__bfloat16_as_ushort(ha) | ((uint32_t)__bfloat16_as_ushort(hb) << 16);
}

// ---------------------------------------------------------------------------
// 1. prep weights: hi/lo bf16 split, [mat][k][n] row-major
// ---------------------------------------------------------------------------
__global__ void prep_weights(const float* __restrict__ Wl,
                             const float* __restrict__ Wr) {
    int idx = blockIdx.x * blockDim.x + threadIdx.x;
    if (idx >= 2 * 128 * 128) return;
    int m2 = idx >> 14;
    int k  = (idx >> 7) & 127;
    int n  = idx & 127;
    float w = (m2 ? Wr : Wl)[k * 128 + n];
    __nv_bfloat16 h = __float2bfloat16(w);
    __nv_bfloat16 l = __float2bfloat16(w - __bfloat162float(h));
    g_W[(m2 * 2 + 0) * 16384 + k * 128 + n] = h;
    g_W[(m2 * 2 + 1) * 16384 + k * 128 + n] = l;
}

// ---------------------------------------------------------------------------
// 2. xconv: x -> fp16 (scatter) + bf16 hi/lo (gemm). Pure bandwidth.
// ---------------------------------------------------------------------------
__global__ __launch_bounds__(256)
void xconv_kernel(const float* __restrict__ x) {
    int i = blockIdx.x * blockDim.x + threadIdx.x;   // one float4 per thread
    if (i >= N_NODES * D / 4) return;
    float4 v = reinterpret_cast<const float4*>(x)[i];
    // fp16 for scatter
    __half2 p0 = __floats2half2_rn(v.x, v.y);
    __half2 p1 = __floats2half2_rn(v.z, v.w);
    reinterpret_cast<uint2*>(g_xh)[i] =
        make_uint2(*reinterpret_cast<uint32_t*>(&p0), *reinterpret_cast<uint32_t*>(&p1));
    // bf16 hi/lo for gemm
    __nv_bfloat16 h0 = __float2bfloat16(v.x), h1 = __float2bfloat16(v.y);
    __nv_bfloat16 h2 = __float2bfloat16(v.z), h3 = __float2bfloat16(v.w);
    uint2 hi = make_uint2(
        (uint32_t)__bfloat16_as_ushort(h0) | ((uint32_t)__bfloat16_as_ushort(h1) << 16),
        (uint32_t)__bfloat16_as_ushort(h2) | ((uint32_t)__bfloat16_as_ushort(h3) << 16));
    uint2 lo = make_uint2(
        pack_bf16x2(v.x - __bfloat162float(h0), v.y - __bfloat162float(h1)),
        pack_bf16x2(v.z - __bfloat162float(h2), v.w - __bfloat162float(h3)));
    reinterpret_cast<uint2*>(g_xhi)[i] = hi;
    reinterpret_cast<uint2*>(g_xlo)[i] = lo;
}

// ---------------------------------------------------------------------------
// 3. edge scatter: one warp per edge; gather fp16 (256B), red fp32 (512B)
// ---------------------------------------------------------------------------
__global__ void scatter_kernel(const int* __restrict__ ei) {
    int warp = (blockIdx.x * blockDim.x + threadIdx.x) >> 5;
    int lane = threadIdx.x & 31;
    if (warp >= N_EDGES) return;
    int src = ei[warp];
    int dst = ei[N_EDGES + warp];
    uint2 hv = reinterpret_cast<const uint2*>(g_xh + (size_t)src * D)[lane];
    __half2 h0 = *reinterpret_cast<__half2*>(&hv.x);
    __half2 h1 = *reinterpret_cast<__half2*>(&hv.y);
    float2 f0 = __half22float2(h0);
    float2 f1 = __half22float2(h1);
    float* dptr = g_sum + (size_t)dst * D + lane * 4;
    asm volatile("red.global.add.v4.f32 [%0], {%1, %2, %3, %4};"
                 :: "l"(dptr), "f"(f0.x), "f"(f0.y), "f"(f1.x), "f"(f1.y)
                 : "memory");
    if (lane == 0) atomicAdd(g_deg + dst, 1.0f);
}

// ---------------------------------------------------------------------------
// 4. meanconv: mean = g_sum/deg -> bf16 hi/lo; re-zero g_sum, g_deg.
//    One warp per node, lane handles 4 cols.
// ---------------------------------------------------------------------------
__global__ __launch_bounds__(256)
void meanconv_kernel() {
    int node = blockIdx.x * 8 + (threadIdx.x >> 5);
    int lane = threadIdx.x & 31;
    float invd = 1.0f / fmaxf(g_deg[node], 1.0f);
    size_t base = (size_t)node * D + lane * 4;
    float4 s = *reinterpret_cast<float4*>(g_sum + base);
    float e0 = s.x * invd, e1 = s.y * invd, e2 = s.z * invd, e3 = s.w * invd;
    __nv_bfloat16 h0 = __float2bfloat16(e0), h1 = __float2bfloat16(e1);
    __nv_bfloat16 h2 = __float2bfloat16(e2), h3 = __float2bfloat16(e3);
    uint2 hi = make_uint2(
        (uint32_t)__bfloat16_as_ushort(h0) | ((uint32_t)__bfloat16_as_ushort(h1) << 16),
        (uint32_t)__bfloat16_as_ushort(h2) | ((uint32_t)__bfloat16_as_ushort(h3) << 16));
    uint2 lo = make_uint2(
        pack_bf16x2(e0 - __bfloat162float(h0), e1 - __bfloat162float(h1)),
        pack_bf16x2(e2 - __bfloat162float(h2), e3 - __bfloat162float(h3)));
    *reinterpret_cast<uint2*>(g_mhi + base) = hi;
    *reinterpret_cast<uint2*>(g_mlo + base) = lo;
    *reinterpret_cast<float4*>(g_sum + base) = make_float4(0.f, 0.f, 0.f, 0.f);
    if (lane == 0) g_deg[node] = 0.f;
}

// ---------------------------------------------------------------------------
// 5. HMMA GEMM: out = x + relu([mean|x] @ [Wl;Wr] + b)
//    All A mats pre-converted bf16 -> pure cp.async + LDSM + MMA.
//    64x128 tile/CTA, 2 CTAs/SM. bf16 hi/lo 3-term compensation.
// ---------------------------------------------------------------------------
#define ASTR 72
#define BSTR 136
#define A_MAT_B (64 * ASTR * 2)       // 9216 B
#define B_MAT_B (64 * BSTR * 2)       // 17408 B
#define SM_A_B (4 * A_MAT_B)          // 36864 B
#define SM_B_B (4 * B_MAT_B)          // 69632 B
#define SMEM_TOTAL (SM_A_B + SM_B_B)  // 106496 B -> 2 CTAs/SM

__global__ __launch_bounds__(256, 2)
void gemm_mma(const float* __restrict__ x,
              const float* __restrict__ bl,
              float* __restrict__ out) {
    extern __shared__ char sm[];
    const uint32_t sA = smem_u32(sm);
    const uint32_t sB = sA + SM_A_B;

    const int tid = threadIdx.x;
    const int lane = tid & 31;
    const int w = tid >> 5;
    const int m0 = blockIdx.x * 64;
    const int mrow0 = (w >> 1) * 16;
    const int ncol0 = (w & 1) * 64;

    float acc[8][4];
    #pragma unroll
    for (int nt = 0; nt < 8; nt++)
        #pragma unroll
        for (int q = 0; q < 4; q++) acc[nt][q] = 0.f;

    #pragma unroll
    for (int c = 0; c < 2; c++) {
        const int k0 = c * 64;
        __syncthreads();    // previous chunk's MMAs done before smem overwrite

        // ---- B: 4 mats x 64k x 128n bf16 via cp.async ----
        #pragma unroll
        for (int i = 0; i < 16; i++) {
            int idx = tid + i * 256;          // 0..4095
            int mat = idx >> 10;
            int rem = idx & 1023;
            int r = rem >> 4, sg = rem & 15;
            uint32_t dst = sB + mat * B_MAT_B + r * (BSTR * 2) + sg * 16;
            const void* src = g_W + mat * 16384 + (k0 + r) * 128 + sg * 8;
            CP_ASYNC16(dst, src);
        }
        // ---- A: 4 mats x 64rows x 64cols bf16 via cp.async (oob zero-fill) ----
        #pragma unroll
        for (int i = 0; i < 8; i++) {
            int idx = tid + i * 256;          // 0..2047
            int mat = idx >> 9;               // 0: mhi, 1: mlo, 2: xhi, 3: xlo
            int rem = idx & 511;
            int r = rem >> 3, sg = rem & 7;
            int row = m0 + r;
            bool valid = row < N_NODES;
            uint32_t dst = sA + mat * A_MAT_B + r * (ASTR * 2) + sg * 16;
            const __nv_bfloat16* base =
                (mat == 0) ? g_mhi : (mat == 1) ? g_mlo : (mat == 2) ? g_xhi : g_xlo;
            const void* src = valid ? (const void*)(base + (size_t)row * D + k0 + sg * 8)
                                    : (const void*)base;
            CP_ASYNC16Z(dst, src, valid ? 16 : 0);
        }
        CP_COMMIT();
        CP_WAIT0();
        __syncthreads();

        // ---- MMA mainloop: 4 k16-steps, 6 compensated MMAs per tile-pair ----
        #pragma unroll
        for (int ks = 0; ks < 4; ks++) {
            const int kk = ks * 16;
            uint32_t a[4][4];
            #pragma unroll
            for (int mat = 0; mat < 4; mat++) {
                uint32_t addr = sA + mat * A_MAT_B
                              + (mrow0 + (lane & 15)) * (ASTR * 2)
                              + (kk + ((lane >> 4) * 8)) * 2;
                LDSM_X4(a[mat], addr);
            }
            #pragma unroll
            for (int np = 0; np < 4; np++) {
                const int ncol = ncol0 + np * 16;
                uint32_t b[4][4];
                #pragma unroll
                for (int mat = 0; mat < 4; mat++) {
                    int quad = lane >> 3;
                    uint32_t addr = sB + mat * B_MAT_B
                                  + (kk + (quad & 1) * 8 + (lane & 7)) * (BSTR * 2)
                                  + (ncol + (quad >> 1) * 8) * 2;
                    LDSM_X4T(b[mat], addr);
                }
                #pragma unroll
                for (int nt = 0; nt < 2; nt++) {
                    float* d = acc[np * 2 + nt];
                    mma16816(d, a[0], b[0] + nt * 2);   // m_hi * Wl_hi
                    mma16816(d, a[1], b[0] + nt * 2);   // m_lo * Wl_hi
                    mma16816(d, a[0], b[1] + nt * 2);   // m_hi * Wl_lo
                    mma16816(d, a[2], b[2] + nt * 2);   // x_hi * Wr_hi
                    mma16816(d, a[3], b[2] + nt * 2);   // x_lo * Wr_hi
                    mma16816(d, a[2], b[3] + nt * 2);   // x_hi * Wr_lo
                }
            }
        }
    }

    // ---- epilogue: out = x + relu(acc + b) ----
    const int rq = lane >> 2;
    const int cq = (lane & 3) * 2;
    #pragma unroll
    for (int h = 0; h < 2; h++) {
        int row = m0 + mrow0 + h * 8 + rq;
        if (row < N_NODES) {
            #pragma unroll
            for (int nt = 0; nt < 8; nt++) {
                int col = ncol0 + nt * 8 + cq;
                float d0 = acc[nt][h * 2 + 0];
                float d1 = acc[nt][h * 2 + 1];
                float2 bv = *reinterpret_cast<const float2*>(bl + col);
                float2 xv = *reinterpret_cast<const float2*>(x + (size_t)row * D + col);
                float2 o;
                o.x = xv.x + fmaxf(d0 + bv.x, 0.f);
                o.y = xv.y + fmaxf(d1 + bv.y, 0.f);
                *reinterpret_cast<float2*>(out + (size_t)row * D + col) = o;
            }
        }
    }
}

// ---------------------------------------------------------------------------
// launch
// ---------------------------------------------------------------------------
extern "C" void kernel_launch(void* const* d_in, const int* in_sizes, int n_in,
                              void* d_out, int out_size) {
    const float* x  = (const float*)d_in[0];
    const int*   ei = (const int*)d_in[1];
    const float* Wl = (const float*)d_in[2];
    const float* bl = (const float*)d_in[3];
    const float* Wr = (const float*)d_in[4];
    float* out = (float*)d_out;
    (void)in_sizes; (void)n_in; (void)out_size;

    // 1. weight prep (hi/lo bf16 split)
    prep_weights<<<(2 * 128 * 128 + 255) / 256, 256>>>(Wl, Wr);

    // 2. x conversion (fp16 + bf16 hi/lo)
    xconv_kernel<<<(N_NODES * D / 4 + 255) / 256, 256>>>(x);

    // 3. edge scatter (fp16 gather, fp32 red; g_sum zeroed by prev meanconv)
    scatter_kernel<<<(N_EDGES * 32 + 255) / 256, 256>>>(ei);

    // 4. mean conversion (re-zeroes g_sum, g_deg)
    meanconv_kernel<<<N_NODES / 8, 256>>>();

    // 5. HMMA dual GEMM + bias + relu + residual
    cudaFuncSetAttribute(gemm_mma, cudaFuncAttributeMaxDynamicSharedMemorySize,
                         SMEM_TOTAL);
    gemm_mma<<<(N_NODES + 63) / 64, 256, SMEM_TOTAL>>>(x, bl, out);
}

// round 9
// speedup vs baseline: 1.1051x; 1.1051x over previous
#include <cuda_runtime.h>
#include <cuda_bf16.h>
#include <cstdint>

#define N_NODES 50000
#define D 128
#define N_EDGES 625000
#define TIL 32
#define NT ((N_NODES + TIL - 1) / TIL)    // 1563 tiles
#define GRID_GEMM 148

// Device-global scratch (allocation-free rule; BSS zero-initialized)
__device__ float g_sum[N_NODES * D];          // re-zeroed by gemm each run
__device__ float g_deg[N_NODES];              // re-zeroed by inv each run
__device__ float g_inv[N_NODES];
__device__ __nv_bfloat16 g_W[4 * 128 * 128];  // Wl_hi, Wl_lo, Wr_hi, Wr_lo  [mat][k][n]

// ---------------------------------------------------------------------------
// helpers
// ---------------------------------------------------------------------------
__device__ __forceinline__ uint32_t smem_u32(const void* p) {
    uint32_t a;
    asm("{ .reg .u64 t; cvta.to.shared.u64 t, %1; cvt.u32.u64 %0, t; }" : "=r"(a) : "l"(p));
    return a;
}

#define CP_ASYNC16(dst, src) \
    asm volatile("cp.async.cg.shared.global [%0], [%1], 16;" :: "r"(dst), "l"(src))
#define CP_COMMIT() asm volatile("cp.async.commit_group;")
#define CP_WAIT0()  asm volatile("cp.async.wait_group 0;" ::: "memory")

#define LDSM_X4(r, addr) \
    asm volatile("ldmatrix.sync.aligned.m8n8.x4.shared.b16 {%0,%1,%2,%3}, [%4];" \
                 : "=r"((r)[0]), "=r"((r)[1]), "=r"((r)[2]), "=r"((r)[3]) : "r"(addr))
#define LDSM_X4T(r, addr) \
    asm volatile("ldmatrix.sync.aligned.m8n8.x4.trans.shared.b16 {%0,%1,%2,%3}, [%4];" \
                 : "=r"((r)[0]), "=r"((r)[1]), "=r"((r)[2]), "=r"((r)[3]) : "r"(addr))

__device__ __forceinline__ void mma16816(float* d, const uint32_t* a, const uint32_t* b) {
    asm volatile(
        "mma.sync.aligned.m16n8k16.row.col.f32.bf16.bf16.f32 "
        "{%0,%1,%2,%3}, {%4,%5,%6,%7}, {%8,%9}, {%0,%1,%2,%3};"
        : "+f"(d[0]), "+f"(d[1]), "+f"(d[2]), "+f"(d[3])
        : "r"(a[0]), "r"(a[1]), "r"(a[2]), "r"(a[3]), "r"(b[0]), "r"(b[1]));
}

__device__ __forceinline__ uint32_t pack_bf16x2(float a, float b) {
    __nv_bfloat16 ha = __float2bfloat16(a), hb = __float2bfloat16(b);
    return (uint32_t)__bfloat16_as_ushort(ha) | ((uint32_t)__bfloat16_as_ushort(hb) << 16);
}

// ---------------------------------------------------------------------------
// 1. prep weights: hi/lo bf16 split, [mat][k][n] row-major
// ---------------------------------------------------------------------------
__global__ void prep_weights(const float* __restrict__ Wl,
                             const float* __restrict__ Wr) {
    int idx = blockIdx.x * blockDim.x + threadIdx.x;
    if (idx >= 2 * 128 * 128) return;
    int m2 = idx >> 14;
    int k  = (idx >> 7) & 127;
    int n  = idx & 127;
    float w = (m2 ? Wr : Wl)[k * 128 + n];
    __nv_bfloat16 h = __float2bfloat16(w);
    __nv_bfloat16 l = __float2bfloat16(w - __bfloat162float(h));
    g_W[(m2 * 2 + 0) * 16384 + k * 128 + n] = h;
    g_W[(m2 * 2 + 1) * 16384 + k * 128 + n] = l;
}

// ---------------------------------------------------------------------------
// 2. edge scatter: one warp per edge, red.global.add.v4.f32
// ---------------------------------------------------------------------------
__global__ void scatter_kernel(const float* __restrict__ x,
                               const int* __restrict__ ei) {
    int warp = (blockIdx.x * blockDim.x + threadIdx.x) >> 5;
    int lane = threadIdx.x & 31;
    if (warp >= N_EDGES) return;
    int src = ei[warp];
    int dst = ei[N_EDGES + warp];
    const float4* xr = reinterpret_cast<const float4*>(x + (size_t)src * D);
    float4 v = xr[lane];
    float* dptr = g_sum + (size_t)dst * D + lane * 4;
    asm volatile("red.global.add.v4.f32 [%0], {%1, %2, %3, %4};"
                 :: "l"(dptr), "f"(v.x), "f"(v.y), "f"(v.z), "f"(v.w)
                 : "memory");
    if (lane == 0) atomicAdd(g_deg + dst, 1.0f);
}

// ---------------------------------------------------------------------------
// 3. inverse degree; re-zeroes g_deg for the next replay
// ---------------------------------------------------------------------------
__global__ void inv_kernel() {
    int i = blockIdx.x * blockDim.x + threadIdx.x;
    if (i < N_NODES) {
        float d = g_deg[i];
        g_inv[i] = 1.0f / fmaxf(d, 1.0f);
        g_deg[i] = 0.0f;
    }
}

// ---------------------------------------------------------------------------
// 4. Persistent HMMA GEMM: out = x + relu([mean|x] @ [Wl;Wr] + b)
//    148 CTAs, 1/SM. All 4 weight mats SMEM-resident (139KB, loaded once).
//    32-row tiles, A double-buffered; register-staged pipeline:
//      issue loads(t+1) -> MMA(t) -> epilogue(t) -> convert+STS(t+1) -> sync
//    bf16 hi/lo 3-term compensation. Re-zeroes g_sum after reading.
// ---------------------------------------------------------------------------
#define BSTR 272                      // bytes per 128-elem bf16 row (256B data + 16B pad)
#define B_MAT_B (128 * BSTR)          // 34816 B
#define A_MAT_B (TIL * BSTR)          // 8704 B
#define SM_B_B (4 * B_MAT_B)          // 139264 B
#define A_BUF_B (4 * A_MAT_B)         // 34816 B
#define SMEM_TOTAL (SM_B_B + 2 * A_BUF_B)   // 208896 B

__global__ __launch_bounds__(256)
void gemm_persist(const float* __restrict__ x,
                  const float* __restrict__ bl,
                  float* __restrict__ out) {
    extern __shared__ char sm[];
    const uint32_t sB = smem_u32(sm);
    const uint32_t sA0 = sB + SM_B_B;

    const int tid = threadIdx.x;
    const int lane = tid & 31;
    const int w = tid >> 5;
    const int mrow0 = (w >> 2) * 16;       // 2 m-groups
    const int ncol0 = (w & 3) * 32;        // 4 n-groups

    // ---- stage all of B once (4 mats x 128k x 128n bf16) via cp.async ----
    #pragma unroll
    for (int i = 0; i < 32; i++) {
        int idx = tid + i * 256;           // 0..8191
        int mat = idx >> 11;
        int rem = idx & 2047;
        int r = rem >> 4, sg = rem & 15;
        uint32_t dst = sB + mat * B_MAT_B + r * BSTR + sg * 16;
        const void* src = g_W + mat * 16384 + r * 128 + sg * 8;
        CP_ASYNC16(dst, src);
    }
    CP_COMMIT();

    // staging thread map: 8 threads per row, 16 cols each
    const int cr = tid >> 3;               // 0..31
    const int cp = tid & 3 | ((tid & 4) << 0);  // 0..7 (just tid&7)
    const int cpart = tid & 7;

    float4 sv[4], xv[4];
    float invd = 1.0f;

    // ---- prologue: load + convert tile t0 into buf0 ----
    int t = blockIdx.x;
    {
        int row = t * TIL + cr;
        bool valid = row < N_NODES;
        const float4* sp = reinterpret_cast<const float4*>(g_sum + (size_t)row * D + cpart * 16);
        const float4* xp = reinterpret_cast<const float4*>(x + (size_t)row * D + cpart * 16);
        invd = valid ? g_inv[row] : 1.0f;
        #pragma unroll
        for (int i = 0; i < 4; i++) {
            sv[i] = valid ? sp[i] : make_float4(0.f, 0.f, 0.f, 0.f);
            xv[i] = valid ? xp[i] : make_float4(0.f, 0.f, 0.f, 0.f);
        }
        if (valid) {   // re-zero g_sum for next replay
            float4* zz = reinterpret_cast<float4*>(g_sum + (size_t)row * D + cpart * 16);
            float4 z = make_float4(0.f, 0.f, 0.f, 0.f);
            #pragma unroll
            for (int i = 0; i < 4; i++) zz[i] = z;
        }
        // convert + STS into buf0
        uint32_t abuf = sA0;
        #pragma unroll
        for (int half = 0; half < 2; half++) {
            uint32_t hiS[4], loS[4], hiX[4], loX[4];
            #pragma unroll
            for (int i = 0; i < 2; i++) {
                float4 s = sv[half * 2 + i];
                float e0 = s.x * invd, e1 = s.y * invd, e2 = s.z * invd, e3 = s.w * invd;
                __nv_bfloat16 h0 = __float2bfloat16(e0), h1 = __float2bfloat16(e1);
                __nv_bfloat16 h2 = __float2bfloat16(e2), h3 = __float2bfloat16(e3);
                hiS[2*i]   = (uint32_t)__bfloat16_as_ushort(h0) | ((uint32_t)__bfloat16_as_ushort(h1) << 16);
                hiS[2*i+1] = (uint32_t)__bfloat16_as_ushort(h2) | ((uint32_t)__bfloat16_as_ushort(h3) << 16);
                loS[2*i]   = pack_bf16x2(e0 - __bfloat162float(h0), e1 - __bfloat162float(h1));
                loS[2*i+1] = pack_bf16x2(e2 - __bfloat162float(h2), e3 - __bfloat162float(h3));
                float4 v = xv[half * 2 + i];
                __nv_bfloat16 g0 = __float2bfloat16(v.x), g1 = __float2bfloat16(v.y);
                __nv_bfloat16 g2 = __float2bfloat16(v.z), g3 = __float2bfloat16(v.w);
                hiX[2*i]   = (uint32_t)__bfloat16_as_ushort(g0) | ((uint32_t)__bfloat16_as_ushort(g1) << 16);
                hiX[2*i+1] = (uint32_t)__bfloat16_as_ushort(g2) | ((uint32_t)__bfloat16_as_ushort(g3) << 16);
                loX[2*i]   = pack_bf16x2(v.x - __bfloat162float(g0), v.y - __bfloat162float(g1));
                loX[2*i+1] = pack_bf16x2(v.z - __bfloat162float(g2), v.w - __bfloat162float(g3));
            }
            uint32_t off = cr * BSTR + cpart * 32 + half * 16;
            *reinterpret_cast<uint4*>(sm + (abuf - sB) + 0 * A_MAT_B + off) = make_uint4(hiS[0], hiS[1], hiS[2], hiS[3]);
            *reinterpret_cast<uint4*>(sm + (abuf - sB) + 1 * A_MAT_B + off) = make_uint4(loS[0], loS[1], loS[2], loS[3]);
            *reinterpret_cast<uint4*>(sm + (abuf - sB) + 2 * A_MAT_B + off) = make_uint4(hiX[0], hiX[1], hiX[2], hiX[3]);
            *reinterpret_cast<uint4*>(sm + (abuf - sB) + 3 * A_MAT_B + off) = make_uint4(loX[0], loX[1], loX[2], loX[3]);
        }
    }
    CP_WAIT0();          // B resident
    __syncthreads();

    int cur = 0;
    for (; t < NT; t += GRID_GEMM) {
        int tn = t + GRID_GEMM;
        bool havenext = tn < NT;

        // ---- 1. issue global loads for tile tn (land under MMA shadow) ----
        if (havenext) {
            int row = tn * TIL + cr;
            bool valid = row < N_NODES;
            const float4* sp = reinterpret_cast<const float4*>(g_sum + (size_t)row * D + cpart * 16);
            const float4* xp = reinterpret_cast<const float4*>(x + (size_t)row * D + cpart * 16);
            invd = valid ? g_inv[row] : 1.0f;
            #pragma unroll
            for (int i = 0; i < 4; i++) {
                sv[i] = valid ? sp[i] : make_float4(0.f, 0.f, 0.f, 0.f);
                xv[i] = valid ? xp[i] : make_float4(0.f, 0.f, 0.f, 0.f);
            }
        }

        // ---- 2. MMA tile t from buf[cur] ----
        float acc[4][4];
        #pragma unroll
        for (int np = 0; np < 4; np++)
            #pragma unroll
            for (int q = 0; q < 4; q++) acc[np][q] = 0.f;

        const uint32_t abuf = sA0 + cur * A_BUF_B;
        #pragma unroll
        for (int ks = 0; ks < 8; ks++) {
            uint32_t a[4][4];
            #pragma unroll
            for (int mat = 0; mat < 4; mat++) {
                uint32_t addr = abuf + mat * A_MAT_B
                              + (mrow0 + (lane & 15)) * BSTR
                              + (ks * 16 + ((lane >> 4) * 8)) * 2;
                LDSM_X4(a[mat], addr);
            }
            #pragma unroll
            for (int np16 = 0; np16 < 2; np16++) {
                const int ncol = ncol0 + np16 * 16;
                uint32_t b[4][4];
                #pragma unroll
                for (int mat = 0; mat < 4; mat++) {
                    int quad = lane >> 3;
                    uint32_t addr = sB + mat * B_MAT_B
                                  + (ks * 16 + (quad & 1) * 8 + (lane & 7)) * BSTR
                                  + (ncol + (quad >> 1) * 8) * 2;
                    LDSM_X4T(b[mat], addr);
                }
                #pragma unroll
                for (int nt = 0; nt < 2; nt++) {
                    float* d = acc[np16 * 2 + nt];
                    mma16816(d, a[0], b[0] + nt * 2);   // m_hi * Wl_hi
                    mma16816(d, a[1], b[0] + nt * 2);   // m_lo * Wl_hi
                    mma16816(d, a[0], b[1] + nt * 2);   // m_hi * Wl_lo
                    mma16816(d, a[2], b[2] + nt * 2);   // x_hi * Wr_hi
                    mma16816(d, a[3], b[2] + nt * 2);   // x_lo * Wr_hi
                    mma16816(d, a[2], b[3] + nt * 2);   // x_hi * Wr_lo
                }
            }
        }

        // ---- 3. epilogue tile t: out = x + relu(acc + b) ----
        {
            const int rq = lane >> 2;
            const int cq = (lane & 3) * 2;
            #pragma unroll
            for (int h = 0; h < 2; h++) {
                int row = t * TIL + mrow0 + h * 8 + rq;
                if (row < N_NODES) {
                    #pragma unroll
                    for (int np = 0; np < 4; np++) {
                        int col = ncol0 + np * 8 + cq;
                        float d0 = acc[np][h * 2 + 0];
                        float d1 = acc[np][h * 2 + 1];
                        float2 bv = *reinterpret_cast<const float2*>(bl + col);
                        float2 xr = *reinterpret_cast<const float2*>(x + (size_t)row * D + col);
                        float2 o;
                        o.x = xr.x + fmaxf(d0 + bv.x, 0.f);
                        o.y = xr.y + fmaxf(d1 + bv.y, 0.f);
                        *reinterpret_cast<float2*>(out + (size_t)row * D + col) = o;
                    }
                }
            }
        }

        // ---- 4. convert + STS tile tn into buf[cur^1]; re-zero g_sum ----
        if (havenext) {
            int row = tn * TIL + cr;
            bool valid = row < N_NODES;
            if (valid) {
                float4* zz = reinterpret_cast<float4*>(g_sum + (size_t)row * D + cpart * 16);
                float4 z = make_float4(0.f, 0.f, 0.f, 0.f);
                #pragma unroll
                for (int i = 0; i < 4; i++) zz[i] = z;
            }
            char* ab = sm + SM_B_B + (cur ^ 1) * A_BUF_B;
            #pragma unroll
            for (int half = 0; half < 2; half++) {
                uint32_t hiS[4], loS[4], hiX[4], loX[4];
                #pragma unroll
                for (int i = 0; i < 2; i++) {
                    float4 s = sv[half * 2 + i];
                    float e0 = s.x * invd, e1 = s.y * invd, e2 = s.z * invd, e3 = s.w * invd;
                    __nv_bfloat16 h0 = __float2bfloat16(e0), h1 = __float2bfloat16(e1);
                    __nv_bfloat16 h2 = __float2bfloat16(e2), h3 = __float2bfloat16(e3);
                    hiS[2*i]   = (uint32_t)__bfloat16_as_ushort(h0) | ((uint32_t)__bfloat16_as_ushort(h1) << 16);
                    hiS[2*i+1] = (uint32_t)__bfloat16_as_ushort(h2) | ((uint32_t)__bfloat16_as_ushort(h3) << 16);
                    loS[2*i]   = pack_bf16x2(e0 - __bfloat162float(h0), e1 - __bfloat162float(h1));
                    loS[2*i+1] = pack_bf16x2(e2 - __bfloat162float(h2), e3 - __bfloat162float(h3));
                    float4 v = xv[half * 2 + i];
                    __nv_bfloat16 g0 = __float2bfloat16(v.x), g1 = __float2bfloat16(v.y);
                    __nv_bfloat16 g2 = __float2bfloat16(v.z), g3 = __float2bfloat16(v.w);
                    hiX[2*i]   = (uint32_t)__bfloat16_as_ushort(g0) | ((uint32_t)__bfloat16_as_ushort(g1) << 16);
                    hiX[2*i+1] = (uint32_t)__bfloat16_as_ushort(g2) | ((uint32_t)__bfloat16_as_ushort(g3) << 16);
                    loX[2*i]   = pack_bf16x2(v.x - __bfloat162float(g0), v.y - __bfloat162float(g1));
                    loX[2*i+1] = pack_bf16x2(v.z - __bfloat162float(g2), v.w - __bfloat162float(g3));
                }
                uint32_t off = cr * BSTR + cpart * 32 + half * 16;
                *reinterpret_cast<uint4*>(ab + 0 * A_MAT_B + off) = make_uint4(hiS[0], hiS[1], hiS[2], hiS[3]);
                *reinterpret_cast<uint4*>(ab + 1 * A_MAT_B + off) = make_uint4(loS[0], loS[1], loS[2], loS[3]);
                *reinterpret_cast<uint4*>(ab + 2 * A_MAT_B + off) = make_uint4(hiX[0], hiX[1], hiX[2], hiX[3]);
                *reinterpret_cast<uint4*>(ab + 3 * A_MAT_B + off) = make_uint4(loX[0], loX[1], loX[2], loX[3]);
            }
        }
        __syncthreads();
        cur ^= 1;
    }
}

// ---------------------------------------------------------------------------
// launch
// ---------------------------------------------------------------------------
extern "C" void kernel_launch(void* const* d_in, const int* in_sizes, int n_in,
                              void* d_out, int out_size) {
    const float* x  = (const float*)d_in[0];
    const int*   ei = (const int*)d_in[1];
    const float* Wl = (const float*)d_in[2];
    const float* bl = (const float*)d_in[3];
    const float* Wr = (const float*)d_in[4];
    float* out = (float*)d_out;
    (void)in_sizes; (void)n_in; (void)out_size;

    // 1. weight prep (hi/lo bf16 split)
    prep_weights<<<(2 * 128 * 128 + 255) / 256, 256>>>(Wl, Wr);

    // 2. edge scatter (1 warp per edge; g_sum zeroed by previous gemm / BSS init)
    scatter_kernel<<<(N_EDGES * 32 + 255) / 256, 256>>>(x, ei);

    // 3. inverse degree (re-zeroes g_deg)
    inv_kernel<<<(N_NODES + 255) / 256, 256>>>();

    // 4. persistent HMMA dual GEMM + bias + relu + residual (re-zeroes g_sum)
    cudaFuncSetAttribute(gemm_persist, cudaFuncAttributeMaxDynamicSharedMemorySize,
                         SMEM_TOTAL);
    gemm_persist<<<GRID_GEMM, 256, SMEM_TOTAL>>>(x, bl, out);
}